// round 12
// baseline (speedup 1.0000x reference)
#include <cuda_runtime.h>
#include <cuda_bf16.h>
#include <mma.h>
#include <cstdint>

using namespace nvcuda;

// ============================================================================
// DETRsmpl head, HMMA bf16 3-term split, sm_103 base.
// R12 = R7 schedule (MR=64, NT=512, 2m x 2n warp tiles) with 64-row k-chunks
//       (half the barrier count) and Hsum in global scratch.
//   u0 = x@W1a ; h_i = relu(u_i + c1 + i*cvec) ; u_{i+1} = u_i + h_i@W231
//   theta = (theta0 + 3 b23) + (h0+h1+h2)@W23
// ============================================================================

#define NT 512
#define MR 64
#define HLD 264      // H/A panel stride (bf16)
#define BLD 264      // B chunk stride (bf16)
#define THLD 164     // theta f32 stride (aliases H region)
#define NTILE 1800

// smem layout (bytes)
#define OFF_H    0        // Hh 33792 | Hl 33792
#define OFF_B    67584    // 2 slots x 67584 (hi 33792 | lo 33792), 64 k-rows
#define OFF_SCR  202752   // 16 warps x 1KB
#define OFF_SB   219136   // bias 256 f32
#define SMEM_SZ  220160

__device__ __nv_bfloat16 g_W1h[256 * 256];    // W1a split
__device__ __nv_bfloat16 g_W1l[256 * 256];
__device__ __nv_bfloat16 g_W231h[256 * 256];  // (W2@W3@W1b) split
__device__ __nv_bfloat16 g_W231l[256 * 256];
__device__ __nv_bfloat16 g_W23h[256 * 192];   // (W2@W3) split, N pad 192
__device__ __nv_bfloat16 g_W23l[256 * 192];
__device__ float g_W23p[256 * 192];
__device__ float g_c1[256];
__device__ float g_cb[3 * 256];               // bias_i = c1 + i*cvec
__device__ float g_b23[160];
__device__ float g_tfin[160];                 // theta0 + 3*b23
__device__ float g_Hs[NTILE * MR * 256];      // per-tile hsum scratch

// ---------------- helpers ----------------
#define CP16(dst, src) asm volatile("cp.async.cg.shared.global [%0], [%1], 16;" :: "r"(dst), "l"(src))
#define CP_COMMIT()    asm volatile("cp.async.commit_group;" ::: "memory")
#define CP_WAIT0()     asm volatile("cp.async.wait_group 0;" ::: "memory")

__device__ __forceinline__ uint32_t pk2(__nv_bfloat16 a, __nv_bfloat16 b) {
    return (uint32_t)__bfloat16_as_ushort(a) | ((uint32_t)__bfloat16_as_ushort(b) << 16);
}

__device__ __forceinline__ void splitstore4(__nv_bfloat16* ph, __nv_bfloat16* pl, float4 v) {
    __nv_bfloat16 h0 = __float2bfloat16(v.x), h1 = __float2bfloat16(v.y);
    __nv_bfloat16 h2 = __float2bfloat16(v.z), h3 = __float2bfloat16(v.w);
    __nv_bfloat16 l0 = __float2bfloat16(v.x - __bfloat162float(h0));
    __nv_bfloat16 l1 = __float2bfloat16(v.y - __bfloat162float(h1));
    __nv_bfloat16 l2 = __float2bfloat16(v.z - __bfloat162float(h2));
    __nv_bfloat16 l3 = __float2bfloat16(v.w - __bfloat162float(h3));
    *reinterpret_cast<uint2*>(ph) = make_uint2(pk2(h0, h1), pk2(h2, h3));
    *reinterpret_cast<uint2*>(pl) = make_uint2(pk2(l0, l1), pk2(l2, l3));
}

// ---------------- prep kernels ----------------
__global__ void prep1_k(const float* __restrict__ W1, const float* __restrict__ b1,
                        const float* __restrict__ W2, const float* __restrict__ b2,
                        const float* __restrict__ W3, const float* __restrict__ b3,
                        const float* __restrict__ icr, const float* __restrict__ ish,
                        const float* __restrict__ icam) {
    __shared__ float sth[160];
    int b = blockIdx.x, t = threadIdx.x;
    if (b < 256) {
        float v = W1[b * 256 + t];
        __nv_bfloat16 h = __float2bfloat16(v);
        __nv_bfloat16 l = __float2bfloat16(v - __bfloat162float(h));
        g_W1h[b * 256 + t] = h;
        g_W1l[b * 256 + t] = l;
    } else if (b < 512) {
        int k = b - 256;
        if (t < 192) {
            float s0 = 0, s1 = 0, s2 = 0, s3 = 0;
            if (t < 157) {
                for (int m = 0; m < 256; m += 4) {
                    s0 = fmaf(W2[k * 256 + m + 0], W3[(m + 0) * 157 + t], s0);
                    s1 = fmaf(W2[k * 256 + m + 1], W3[(m + 1) * 157 + t], s1);
                    s2 = fmaf(W2[k * 256 + m + 2], W3[(m + 2) * 157 + t], s2);
                    s3 = fmaf(W2[k * 256 + m + 3], W3[(m + 3) * 157 + t], s3);
                }
            }
            float v = (s0 + s1) + (s2 + s3);
            g_W23p[k * 192 + t] = v;
            __nv_bfloat16 h = __float2bfloat16(v);
            __nv_bfloat16 l = __float2bfloat16(v - __bfloat162float(h));
            g_W23h[k * 192 + t] = h;
            g_W23l[k * 192 + t] = l;
        }
    } else if (b == 512) {
        if (t < 160) {
            float v = 0.f;
            if (t < 144) v = icr[t];
            else if (t < 154) v = ish[t - 144];
            else if (t < 157) v = icam[t - 154];
            sth[t] = v;
        }
        __syncthreads();
        float s = b1[t];
        for (int k = 0; k < 157; k++)
            s = fmaf(sth[k], W1[(256 + k) * 256 + t], s);
        g_c1[t] = s;
    } else {
        if (t < 160) {
            float s = 0.f;
            if (t < 157) {
                s = b3[t];
                for (int m = 0; m < 256; m++)
                    s = fmaf(b2[m], W3[m * 157 + t], s);
            }
            g_b23[t] = s;
            float v = 0.f;
            if (t < 144) v = icr[t];
            else if (t < 154) v = ish[t - 144];
            else if (t < 157) v = icam[t - 154];
            g_tfin[t] = v + 3.f * s;
        }
    }
}

__global__ void prep2_k(const float* __restrict__ W1) {
    int b = blockIdx.x, t = threadIdx.x;
    if (b < 256) {
        float s = 0.f;
        for (int k = 0; k < 157; k++)
            s = fmaf(g_W23p[b * 192 + k], W1[(256 + k) * 256 + t], s);
        __nv_bfloat16 h = __float2bfloat16(s);
        __nv_bfloat16 l = __float2bfloat16(s - __bfloat162float(h));
        g_W231h[b * 256 + t] = h;
        g_W231l[b * 256 + t] = l;
    } else {
        float cv = 0.f;
        for (int k = 0; k < 157; k++)
            cv = fmaf(g_b23[k], W1[(256 + k) * 256 + t], cv);
        float c1 = g_c1[t];
        g_cb[0 * 256 + t] = c1;
        g_cb[1 * 256 + t] = c1 + cv;
        g_cb[2 * 256 + t] = c1 + 2.f * cv;
    }
}

// ---------------- main kernel ----------------
typedef wmma::fragment<wmma::matrix_a, 16, 16, 16, __nv_bfloat16, wmma::row_major> FragA;
typedef wmma::fragment<wmma::matrix_b, 16, 16, 16, __nv_bfloat16, wmma::row_major> FragB;
typedef wmma::fragment<wmma::accumulator, 16, 16, 16, float> FragC;

__global__ __launch_bounds__(NT, 1)
void detr_wmma(const float* __restrict__ x, float* __restrict__ out, int nrows) {
    extern __shared__ char smc[];
    __nv_bfloat16* Hh = reinterpret_cast<__nv_bfloat16*>(smc + OFF_H);
    __nv_bfloat16* Hl = reinterpret_cast<__nv_bfloat16*>(smc + OFF_H + 33792);
    float* scr = reinterpret_cast<float*>(smc + OFF_SCR);
    float* sbias = reinterpret_cast<float*>(smc + OFF_SB);

    const int tid = threadIdx.x;
    const int w = tid >> 5, lane = tid & 31;
    const int mg = w >> 3, ng = w & 7;       // u-GEMM: 2m x 2n warp tile
    const int row0 = blockIdx.x * MR;
    float* wscr = scr + w * 256;
    float* hsBase = g_Hs + (size_t)blockIdx.x * (MR * 256);

    // stage a 64-row x 256-col (hi|lo) B chunk: 4096 CP16, 8/thread
    auto stageB = [&](const __nv_bfloat16* hi, const __nv_bfloat16* lo, int kc, int buf) {
        uint32_t dbase = (uint32_t)__cvta_generic_to_shared(smc + OFF_B + buf * 67584);
#pragma unroll
        for (int i = 0; i < 8; i++) {
            int idx = tid + i * NT;           // 0..4095
            int half = idx >> 11, e = idx & 2047;
            int row = e >> 5, col = e & 31;   // 64 rows x 32 groups
            const __nv_bfloat16* src = (half ? lo : hi) + (size_t)(kc * 64 + row) * 256 + col * 8;
            uint32_t dst = dbase + half * 33792 + (row * BLD + col * 8) * 2;
            CP16(dst, src);
        }
    };
    // stage a 64-row x 192-col (hi|lo) chunk (W23): 3072 CP16, 6/thread
    auto stageBd = [&](int kc, int buf) {
        uint32_t dbase = (uint32_t)__cvta_generic_to_shared(smc + OFF_B + buf * 67584);
#pragma unroll
        for (int i = 0; i < 6; i++) {
            int idx = tid + i * NT;           // 0..3071
            int half = idx >= 1536, e = idx - half * 1536;  // 0..1535
            int row = e / 24, col = e - row * 24;           // 64 rows x 24 groups
            const __nv_bfloat16* src = (half ? g_W23l : g_W23h) + (size_t)(kc * 64 + row) * 192 + col * 8;
            uint32_t dst = dbase + half * 33792 + (row * BLD + col * 8) * 2;
            CP16(dst, src);
        }
    };
    // u/W231 chunk MMA: warp tile 2m x 2n, 64-row chunk = 4 ks steps
    auto mmaChunk = [&](FragC* acc, int kc, int buf) {
        const __nv_bfloat16* Bh = reinterpret_cast<const __nv_bfloat16*>(smc + OFF_B + buf * 67584);
        const __nv_bfloat16* Bl = reinterpret_cast<const __nv_bfloat16*>(smc + OFF_B + buf * 67584 + 33792);
        FragA fah, fal;
        FragB fb0h, fb0l, fb1h, fb1l;
#pragma unroll
        for (int ks = 0; ks < 4; ks++) {
            const int kg = kc * 64 + ks * 16;
            wmma::load_matrix_sync(fb0h, Bh + ks * 16 * BLD + (ng * 2 + 0) * 16, BLD);
            wmma::load_matrix_sync(fb0l, Bl + ks * 16 * BLD + (ng * 2 + 0) * 16, BLD);
            wmma::load_matrix_sync(fb1h, Bh + ks * 16 * BLD + (ng * 2 + 1) * 16, BLD);
            wmma::load_matrix_sync(fb1l, Bl + ks * 16 * BLD + (ng * 2 + 1) * 16, BLD);
#pragma unroll
            for (int mi = 0; mi < 2; mi++) {
                wmma::load_matrix_sync(fah, Hh + (mg * 2 + mi) * 16 * HLD + kg, HLD);
                wmma::load_matrix_sync(fal, Hl + (mg * 2 + mi) * 16 * HLD + kg, HLD);
                wmma::mma_sync(acc[mi * 2 + 0], fah, fb0h, acc[mi * 2 + 0]);
                wmma::mma_sync(acc[mi * 2 + 0], fah, fb0l, acc[mi * 2 + 0]);
                wmma::mma_sync(acc[mi * 2 + 0], fal, fb0h, acc[mi * 2 + 0]);
                wmma::mma_sync(acc[mi * 2 + 1], fah, fb1h, acc[mi * 2 + 1]);
                wmma::mma_sync(acc[mi * 2 + 1], fah, fb1l, acc[mi * 2 + 1]);
                wmma::mma_sync(acc[mi * 2 + 1], fal, fb1h, acc[mi * 2 + 1]);
            }
        }
    };

    // ---- stage x split into panels + prefetch W1a chunk 0 ----
    stageB(g_W1h, g_W1l, 0, 0); CP_COMMIT();
    {
        const int r = tid >> 3, c0 = tid & 7;
        const float* xr = x + (size_t)(row0 + r) * 256;
#pragma unroll
        for (int q = 0; q < 8; q++) {
            const int c4 = c0 + 8 * q;
            float4 v = *reinterpret_cast<const float4*>(xr + c4 * 4);
            splitstore4(&Hh[r * HLD + c4 * 4], &Hl[r * HLD + c4 * 4], v);
        }
    }
    CP_WAIT0(); __syncthreads();

    // ---- u0 = x @ W1a (4 chunks of 64 k-rows) ----
    FragC acc[4];
#pragma unroll
    for (int i = 0; i < 4; i++) wmma::fill_fragment(acc[i], 0.f);
    for (int kc = 0; kc < 4; kc++) {
        if (kc < 3) { stageB(g_W1h, g_W1l, kc + 1, (kc + 1) & 1); CP_COMMIT(); }
        mmaChunk(acc, kc, kc & 1);
        CP_WAIT0(); __syncthreads();
    }

    // ---- 3 iterations ----
    for (int it = 0; it < 3; it++) {
        if (tid < 256) sbias[tid] = g_cb[it * 256 + tid];
        if (it < 2) stageB(g_W231h, g_W231l, 0, 0); else stageBd(0, 0);
        CP_COMMIT();
        __syncthreads();

        // conversion: h = relu(acc + bias); Hs accumulate (global); panels <- h (or hsum+h)
#pragma unroll
        for (int mi = 0; mi < 2; mi++) {
#pragma unroll
            for (int nj = 0; nj < 2; nj++) {
                wmma::store_matrix_sync(wscr, acc[mi * 2 + nj], 16, wmma::mem_row_major);
                __syncwarp();
                const int gr = (mg * 2 + mi) * 16, gc = (ng * 2 + nj) * 16;
#pragma unroll
                for (int e = 0; e < 8; e++) {
                    int idx = lane * 8 + e;
                    int r = idx >> 4, c = idx & 15;
                    int row = gr + r, col = gc + c;
                    float h = fmaxf(wscr[r * 16 + c] + sbias[col], 0.f);
                    float* hp = hsBase + row * 256 + col;
                    if (it == 0) *hp = h;
                    else if (it == 1) *hp += h;
                    else h += *hp;
                    __nv_bfloat16 hh = __float2bfloat16(h);
                    __nv_bfloat16 hl = __float2bfloat16(h - __bfloat162float(hh));
                    Hh[row * HLD + col] = hh;
                    Hl[row * HLD + col] = hl;
                }
                __syncwarp();
            }
        }
        CP_WAIT0(); __syncthreads();

        if (it < 2) {
            for (int kc = 0; kc < 4; kc++) {
                if (kc < 3) { stageB(g_W231h, g_W231l, kc + 1, (kc + 1) & 1); CP_COMMIT(); }
                mmaChunk(acc, kc, kc & 1);
                CP_WAIT0(); __syncthreads();
            }
        }
    }

    // ---- delta = Hsum_panels @ W23 (4m x 12n; warp: 1m x 3n) ----
    const int mgd = w & 3, ngd = w >> 2;
    FragC dacc[3];
#pragma unroll
    for (int j = 0; j < 3; j++) wmma::fill_fragment(dacc[j], 0.f);
    for (int kc = 0; kc < 4; kc++) {
        if (kc < 3) { stageBd(kc + 1, (kc + 1) & 1); CP_COMMIT(); }
        {
            const int buf = kc & 1;
            const __nv_bfloat16* Bh = reinterpret_cast<const __nv_bfloat16*>(smc + OFF_B + buf * 67584);
            const __nv_bfloat16* Bl = reinterpret_cast<const __nv_bfloat16*>(smc + OFF_B + buf * 67584 + 33792);
            FragA fah, fal;
            FragB fbh, fbl;
#pragma unroll
            for (int ks = 0; ks < 4; ks++) {
                const int kg = kc * 64 + ks * 16;
                wmma::load_matrix_sync(fah, Hh + mgd * 16 * HLD + kg, HLD);
                wmma::load_matrix_sync(fal, Hl + mgd * 16 * HLD + kg, HLD);
#pragma unroll
                for (int j = 0; j < 3; j++) {
                    const int n = ngd + 4 * j;
                    wmma::load_matrix_sync(fbh, Bh + ks * 16 * BLD + n * 16, BLD);
                    wmma::load_matrix_sync(fbl, Bl + ks * 16 * BLD + n * 16, BLD);
                    wmma::mma_sync(dacc[j], fah, fbh, dacc[j]);
                    wmma::mma_sync(dacc[j], fah, fbl, dacc[j]);
                    wmma::mma_sync(dacc[j], fal, fbh, dacc[j]);
                }
            }
        }
        CP_WAIT0(); __syncthreads();
    }

    // ---- theta = tfin + dacc, into H region (panels dead) ----
    float* th = reinterpret_cast<float*>(smc + OFF_H);
#pragma unroll
    for (int j = 0; j < 3; j++) {
        const int n = ngd + 4 * j;
        if (n < 10) {
            wmma::store_matrix_sync(wscr, dacc[j], 16, wmma::mem_row_major);
            __syncwarp();
#pragma unroll
            for (int e = 0; e < 8; e++) {
                int idx = lane * 8 + e;
                int r = idx >> 4, c = idx & 15;
                th[(mgd * 16 + r) * THLD + n * 16 + c] =
                    wscr[r * 16 + c] + g_tfin[n * 16 + c];
            }
            __syncwarp();
        }
    }
    __syncthreads();

    // ---- epilogue: rot6d -> rotmat, betas, camera ----
    float* out_rot  = out;
    float* out_beta = out + (size_t)nrows * 216;
    float* out_cam  = out + (size_t)nrows * 226;

    for (int idx = tid; idx < MR * 24; idx += NT) {
        int r = idx / 24, g = idx - 24 * r;
        const float* tp = &th[r * THLD + g * 6];
        float a1x = tp[0], a2x = tp[1];
        float a1y = tp[2], a2y = tp[3];
        float a1z = tp[4], a2z = tp[5];
        float n1 = sqrtf(a1x * a1x + a1y * a1y + a1z * a1z);
        float i1 = 1.f / fmaxf(n1, 1e-12f);
        float b1x = a1x * i1, b1y = a1y * i1, b1z = a1z * i1;
        float d = b1x * a2x + b1y * a2y + b1z * a2z;
        float c2x = a2x - d * b1x, c2y = a2y - d * b1y, c2z = a2z - d * b1z;
        float n2 = sqrtf(c2x * c2x + c2y * c2y + c2z * c2z);
        float i2 = 1.f / fmaxf(n2, 1e-12f);
        float b2x = c2x * i2, b2y = c2y * i2, b2z = c2z * i2;
        float b3x = b1y * b2z - b1z * b2y;
        float b3y = b1z * b2x - b1x * b2z;
        float b3z = b1x * b2y - b1y * b2x;
        float* o = out_rot + (size_t)(row0 + r) * 216 + g * 9;
        o[0] = b1x; o[1] = b2x; o[2] = b3x;
        o[3] = b1y; o[4] = b2y; o[5] = b3y;
        o[6] = b1z; o[7] = b2z; o[8] = b3z;
    }
    for (int idx = tid; idx < MR * 13; idx += NT) {
        int r = idx / 13, c = idx - 13 * r;
        if (c < 10)
            out_beta[(size_t)(row0 + r) * 10 + c] = th[r * THLD + 144 + c];
        else
            out_cam[(size_t)(row0 + r) * 3 + (c - 10)] = th[r * THLD + 154 + (c - 10)];
    }
}

// ---------------- launch ----------------
extern "C" void kernel_launch(void* const* d_in, const int* in_sizes, int n_in,
                              void* d_out, int out_size) {
    const float* x    = (const float*)d_in[0];
    const float* W1   = (const float*)d_in[2];
    const float* b1   = (const float*)d_in[3];
    const float* W2   = (const float*)d_in[4];
    const float* b2   = (const float*)d_in[5];
    const float* W3   = (const float*)d_in[6];
    const float* b3   = (const float*)d_in[7];
    const float* icr  = (const float*)d_in[8];
    const float* ish  = (const float*)d_in[9];
    const float* icam = (const float*)d_in[10];
    float* out = (float*)d_out;

    int nrows = in_sizes[0] / 256;  // 115200

    prep1_k<<<514, 256>>>(W1, b1, W2, b2, W3, b3, icr, ish, icam);
    prep2_k<<<257, 256>>>(W1);

    cudaFuncSetAttribute(detr_wmma, cudaFuncAttributeMaxDynamicSharedMemorySize, SMEM_SZ);
    detr_wmma<<<NTILE, NT, SMEM_SZ>>>(x, out, nrows);
}

// round 13
// speedup vs baseline: 1.3194x; 1.3194x over previous
#include <cuda_runtime.h>
#include <cuda_bf16.h>
#include <mma.h>
#include <cstdint>

using namespace nvcuda;

// ============================================================================
// DETRsmpl head, HMMA bf16 3-term split, sm_103 base.
// R13 = R7 main kernel VERBATIM (champion, 1004us) + single fused prep kernel
//       (W231 computed block-locally as W2@(W3@W1b); no second launch).
//   u0 = x@W1a ; h_i = relu(u_i + c1 + i*cvec) ; u_{i+1} = u_i + h_i@W231
//   theta = (theta0 + 3 b23) + (h0+h1+h2)@W23
// 64 rows/CTA, 1800 CTAs, 512 threads. acc persistent in registers.
// ============================================================================

#define NT 512
#define MR 64
#define HLD 264      // H/A panel stride (bf16)
#define HS_LD 260    // Hsum f32 stride
#define BLD 264      // 256-wide B chunk stride (bf16)
#define BLD2 200     // 192-wide B chunk stride (bf16)

// smem layout (bytes)
#define OFF_H    0        // Hh 33792 | Hl 33792
#define OFF_HS   67584    // Hsum f32 64x260 = 66560 (reused as theta at end)
#define OFF_B    134144   // 2 x 33792
#define OFF_SCR  201728   // 16 x 256 f32
#define OFF_SB   218112   // bias 256 f32
#define SMEM_SZ  219136

__device__ __nv_bfloat16 g_W1h[256 * 256];    // W1a split
__device__ __nv_bfloat16 g_W1l[256 * 256];
__device__ __nv_bfloat16 g_W231h[256 * 256];  // (W2@W3@W1b) split
__device__ __nv_bfloat16 g_W231l[256 * 256];
__device__ __nv_bfloat16 g_W23h[256 * 192];   // (W2@W3) split, N pad 192
__device__ __nv_bfloat16 g_W23l[256 * 192];
__device__ float g_cb[3 * 256];               // bias_i = c1 + i*cvec
__device__ float g_tfin[160];                 // theta0 + 3*b23

// ---------------- helpers ----------------
#define CP16(dst, src) asm volatile("cp.async.cg.shared.global [%0], [%1], 16;" :: "r"(dst), "l"(src))
#define CP_COMMIT()    asm volatile("cp.async.commit_group;" ::: "memory")
#define CP_WAIT0()     asm volatile("cp.async.wait_group 0;" ::: "memory")

__device__ __forceinline__ uint32_t pk2(__nv_bfloat16 a, __nv_bfloat16 b) {
    return (uint32_t)__bfloat16_as_ushort(a) | ((uint32_t)__bfloat16_as_ushort(b) << 16);
}

__device__ __forceinline__ void splitstore4(__nv_bfloat16* ph, __nv_bfloat16* pl, float4 v) {
    __nv_bfloat16 h0 = __float2bfloat16(v.x), h1 = __float2bfloat16(v.y);
    __nv_bfloat16 h2 = __float2bfloat16(v.z), h3 = __float2bfloat16(v.w);
    __nv_bfloat16 l0 = __float2bfloat16(v.x - __bfloat162float(h0));
    __nv_bfloat16 l1 = __float2bfloat16(v.y - __bfloat162float(h1));
    __nv_bfloat16 l2 = __float2bfloat16(v.z - __bfloat162float(h2));
    __nv_bfloat16 l3 = __float2bfloat16(v.w - __bfloat162float(h3));
    *reinterpret_cast<uint2*>(ph) = make_uint2(pk2(h0, h1), pk2(h2, h3));
    *reinterpret_cast<uint2*>(pl) = make_uint2(pk2(l0, l1), pk2(l2, l3));
}

// ---------------- single fused prep kernel ----------------
// blocks 0..255   : W1a row split
// blocks 256..511 : k=b-256: W23p row k (block-local smem) -> W23 split row
//                   -> W231 row k = W23p_row @ W1b (block-local, no 2nd launch)
// block 512       : theta0, b23 (local) -> cb vectors, tfin
__global__ void prep_k(const float* __restrict__ W1, const float* __restrict__ b1,
                       const float* __restrict__ W2, const float* __restrict__ b2,
                       const float* __restrict__ W3, const float* __restrict__ b3,
                       const float* __restrict__ icr, const float* __restrict__ ish,
                       const float* __restrict__ icam) {
    __shared__ float srow[192];
    __shared__ float sth[160];
    int b = blockIdx.x, t = threadIdx.x;
    if (b < 256) {
        float v = W1[b * 256 + t];
        __nv_bfloat16 h = __float2bfloat16(v);
        __nv_bfloat16 l = __float2bfloat16(v - __bfloat162float(h));
        g_W1h[b * 256 + t] = h;
        g_W1l[b * 256 + t] = l;
    } else if (b < 512) {
        int k = b - 256;
        if (t < 192) {
            float s0 = 0, s1 = 0, s2 = 0, s3 = 0;
            if (t < 157) {
                for (int m = 0; m < 256; m += 4) {
                    s0 = fmaf(W2[k * 256 + m + 0], W3[(m + 0) * 157 + t], s0);
                    s1 = fmaf(W2[k * 256 + m + 1], W3[(m + 1) * 157 + t], s1);
                    s2 = fmaf(W2[k * 256 + m + 2], W3[(m + 2) * 157 + t], s2);
                    s3 = fmaf(W2[k * 256 + m + 3], W3[(m + 3) * 157 + t], s3);
                }
            }
            float v = (s0 + s1) + (s2 + s3);
            srow[t] = v;
            __nv_bfloat16 h = __float2bfloat16(v);
            __nv_bfloat16 l = __float2bfloat16(v - __bfloat162float(h));
            g_W23h[k * 192 + t] = h;
            g_W23l[k * 192 + t] = l;
        }
        __syncthreads();
        // W231 row k = srow[0..156] @ W1b   (W1b row j = W1 row 256+j)
        float s = 0.f;
        for (int j = 0; j < 157; j++)
            s = fmaf(srow[j], W1[(256 + j) * 256 + t], s);
        __nv_bfloat16 h = __float2bfloat16(s);
        __nv_bfloat16 l = __float2bfloat16(s - __bfloat162float(h));
        g_W231h[k * 256 + t] = h;
        g_W231l[k * 256 + t] = l;
    } else {
        // theta0 and b23 locally
        if (t < 160) {
            float v = 0.f;
            if (t < 144) v = icr[t];
            else if (t < 154) v = ish[t - 144];
            else if (t < 157) v = icam[t - 154];
            sth[t] = v;
            float s = 0.f;
            if (t < 157) {
                s = b3[t];
                for (int m = 0; m < 256; m++)
                    s = fmaf(b2[m], W3[m * 157 + t], s);
            }
            srow[t] = s;                       // b23 (padded 0)
            g_tfin[t] = v + 3.f * s;
        }
        __syncthreads();
        float c1 = b1[t];
        float cv = 0.f;
        for (int j = 0; j < 157; j++) {
            float w = W1[(256 + j) * 256 + t];
            c1 = fmaf(sth[j], w, c1);
            cv = fmaf(srow[j], w, cv);
        }
        g_cb[0 * 256 + t] = c1;
        g_cb[1 * 256 + t] = c1 + cv;
        g_cb[2 * 256 + t] = c1 + 2.f * cv;
    }
}

// ---------------- main kernel (R7 verbatim) ----------------
typedef wmma::fragment<wmma::matrix_a, 16, 16, 16, __nv_bfloat16, wmma::row_major> FragA;
typedef wmma::fragment<wmma::matrix_b, 16, 16, 16, __nv_bfloat16, wmma::row_major> FragB;
typedef wmma::fragment<wmma::accumulator, 16, 16, 16, float> FragC;

__global__ __launch_bounds__(NT, 1)
void detr_wmma(const float* __restrict__ x, float* __restrict__ out, int nrows) {
    extern __shared__ char smc[];
    __nv_bfloat16* Hh = reinterpret_cast<__nv_bfloat16*>(smc + OFF_H);
    __nv_bfloat16* Hl = reinterpret_cast<__nv_bfloat16*>(smc + OFF_H + 33792);
    float* Hs = reinterpret_cast<float*>(smc + OFF_HS);
    float* scr = reinterpret_cast<float*>(smc + OFF_SCR);
    float* sbias = reinterpret_cast<float*>(smc + OFF_SB);

    const int tid = threadIdx.x;
    const int w = tid >> 5, lane = tid & 31;
    const int mg = w >> 3, ng = w & 7;       // u-GEMM: 2m x 2n warp tile
    const int row0 = blockIdx.x * MR;
    float* wscr = scr + w * 256;

    // 256-wide B chunk stage (hi|lo), 32 k-rows
    auto stageB256 = [&](const __nv_bfloat16* hi, const __nv_bfloat16* lo,
                         int kc, int buf) {
        uint32_t dbase = (uint32_t)__cvta_generic_to_shared(smc + OFF_B + buf * 33792);
#pragma unroll
        for (int i = 0; i < 4; i++) {
            int idx = tid + i * NT;
            int half = idx >> 10, e = idx & 1023;
            int row = e >> 5, col = e & 31;
            const __nv_bfloat16* src = (half ? lo : hi) + (size_t)(kc * 32 + row) * 256 + col * 8;
            uint32_t dst = dbase + half * 16896 + (row * BLD + col * 8) * 2;
            CP16(dst, src);
        }
    };
    // 192-wide B chunk stage
    auto stageB192 = [&](int kc, int buf) {
        uint32_t dbase = (uint32_t)__cvta_generic_to_shared(smc + OFF_B + buf * 33792);
#pragma unroll
        for (int i = 0; i < 3; i++) {
            int idx = tid + i * NT;
            int half = idx >= 768, e = idx - half * 768;
            int row = e / 24, col = e - row * 24;
            const __nv_bfloat16* src =
                (half ? g_W23l : g_W23h) + (size_t)(kc * 32 + row) * 192 + col * 8;
            uint32_t dst = dbase + half * 16896 + (row * BLD2 + col * 8) * 2;
            CP16(dst, src);
        }
    };
    // u-GEMM chunk: A = panels (full K), B = staged chunk; 2m x 2n, 3-term
    auto mmaChunk2 = [&](FragC* acc, int kc, int buf) {
        const __nv_bfloat16* Bh = reinterpret_cast<const __nv_bfloat16*>(smc + OFF_B + buf * 33792);
        const __nv_bfloat16* Bl = reinterpret_cast<const __nv_bfloat16*>(smc + OFF_B + buf * 33792 + 16896);
        FragA fah, fal;
        FragB fb0h, fb0l, fb1h, fb1l;
#pragma unroll
        for (int ks = 0; ks < 2; ks++) {
            const int kg = kc * 32 + ks * 16;
            wmma::load_matrix_sync(fb0h, Bh + ks * 16 * BLD + (ng * 2 + 0) * 16, BLD);
            wmma::load_matrix_sync(fb0l, Bl + ks * 16 * BLD + (ng * 2 + 0) * 16, BLD);
            wmma::load_matrix_sync(fb1h, Bh + ks * 16 * BLD + (ng * 2 + 1) * 16, BLD);
            wmma::load_matrix_sync(fb1l, Bl + ks * 16 * BLD + (ng * 2 + 1) * 16, BLD);
#pragma unroll
            for (int mi = 0; mi < 2; mi++) {
                wmma::load_matrix_sync(fah, Hh + (mg * 2 + mi) * 16 * HLD + kg, HLD);
                wmma::load_matrix_sync(fal, Hl + (mg * 2 + mi) * 16 * HLD + kg, HLD);
                wmma::mma_sync(acc[mi * 2 + 0], fah, fb0h, acc[mi * 2 + 0]);
                wmma::mma_sync(acc[mi * 2 + 0], fah, fb0l, acc[mi * 2 + 0]);
                wmma::mma_sync(acc[mi * 2 + 0], fal, fb0h, acc[mi * 2 + 0]);
                wmma::mma_sync(acc[mi * 2 + 1], fah, fb1h, acc[mi * 2 + 1]);
                wmma::mma_sync(acc[mi * 2 + 1], fah, fb1l, acc[mi * 2 + 1]);
                wmma::mma_sync(acc[mi * 2 + 1], fal, fb1h, acc[mi * 2 + 1]);
            }
        }
    };

    // ---- stage x split into panels (once) + prefetch W1a chunk 0 ----
    stageB256(g_W1h, g_W1l, 0, 0); CP_COMMIT();
    {
        const int r = tid >> 3, c0 = tid & 7;
        const float* xr = x + (size_t)(row0 + r) * 256;
#pragma unroll
        for (int q = 0; q < 8; q++) {
            const int c4 = c0 + 8 * q;
            float4 v = *reinterpret_cast<const float4*>(xr + c4 * 4);
            splitstore4(&Hh[r * HLD + c4 * 4], &Hl[r * HLD + c4 * 4], v);
        }
    }
    CP_WAIT0(); __syncthreads();

    // ---- phase A: acc = x @ W1a ----
    FragC acc[4];
#pragma unroll
    for (int i = 0; i < 4; i++) wmma::fill_fragment(acc[i], 0.f);
    for (int kc = 0; kc < 8; kc++) {
        const int cb = kc & 1;
        if (kc < 7) { stageB256(g_W1h, g_W1l, kc + 1, cb ^ 1); CP_COMMIT(); }
        mmaChunk2(acc, kc, cb);
        CP_WAIT0(); __syncthreads();
    }

    // ---- 3 iterations: convert + (it<2) acc += h @ W231 ----
    for (int it = 0; it < 3; it++) {
        if (tid < 256) sbias[tid] = g_cb[it * 256 + tid];
        if (it < 2) stageB256(g_W231h, g_W231l, 0, 0); else stageB192(0, 0);
        CP_COMMIT();
        __syncthreads();

        // h = relu(acc + bias); panels <- (it<2 ? h : Hsum + h); Hsum accumulate
#pragma unroll
        for (int mi = 0; mi < 2; mi++) {
#pragma unroll
            for (int nj = 0; nj < 2; nj++) {
                wmma::store_matrix_sync(wscr, acc[mi * 2 + nj], 16, wmma::mem_row_major);
                __syncwarp();
                const int gr = (mg * 2 + mi) * 16, gc = (ng * 2 + nj) * 16;
#pragma unroll
                for (int e = 0; e < 8; e++) {
                    int idx = lane * 8 + e;
                    int r = idx >> 4, c = idx & 15;
                    int row = gr + r, col = gc + c;
                    float h = fmaxf(wscr[r * 16 + c] + sbias[col], 0.f);
                    if (it == 0) Hs[row * HS_LD + col] = h;
                    else if (it == 1) Hs[row * HS_LD + col] += h;
                    else h += Hs[row * HS_LD + col];
                    __nv_bfloat16 hh = __float2bfloat16(h);
                    __nv_bfloat16 hl = __float2bfloat16(h - __bfloat162float(hh));
                    Hh[row * HLD + col] = hh;
                    Hl[row * HLD + col] = hl;
                }
                __syncwarp();
            }
        }
        CP_WAIT0(); __syncthreads();

        if (it < 2) {
            for (int kc = 0; kc < 8; kc++) {
                const int cb = kc & 1;
                if (kc < 7) { stageB256(g_W231h, g_W231l, kc + 1, cb ^ 1); CP_COMMIT(); }
                mmaChunk2(acc, kc, cb);
                CP_WAIT0(); __syncthreads();
            }
        }
    }

    // ---- final delta: dacc = Hsum_panels @ W23 (N=192, warp: 1m x 3n) ----
    const int dm = w & 3, ng3 = w >> 2;
    FragC dacc[3];
#pragma unroll
    for (int j = 0; j < 3; j++) wmma::fill_fragment(dacc[j], 0.f);

    for (int kc = 0; kc < 8; kc++) {
        const int cb = kc & 1;
        if (kc < 7) { stageB192(kc + 1, cb ^ 1); CP_COMMIT(); }
        {
            const __nv_bfloat16* Bh = reinterpret_cast<const __nv_bfloat16*>(smc + OFF_B + cb * 33792);
            const __nv_bfloat16* Bl = reinterpret_cast<const __nv_bfloat16*>(smc + OFF_B + cb * 33792 + 16896);
            FragA fah, fal;
            FragB fbh, fbl;
#pragma unroll
            for (int ks = 0; ks < 2; ks++) {
                const int kg = kc * 32 + ks * 16;
                wmma::load_matrix_sync(fah, Hh + dm * 16 * HLD + kg, HLD);
                wmma::load_matrix_sync(fal, Hl + dm * 16 * HLD + kg, HLD);
#pragma unroll
                for (int j = 0; j < 3; j++) {
                    const int n = ng3 + 4 * j;
                    wmma::load_matrix_sync(fbh, Bh + ks * 16 * BLD2 + n * 16, BLD2);
                    wmma::load_matrix_sync(fbl, Bl + ks * 16 * BLD2 + n * 16, BLD2);
                    wmma::mma_sync(dacc[j], fah, fbh, dacc[j]);
                    wmma::mma_sync(dacc[j], fah, fbl, dacc[j]);
                    wmma::mma_sync(dacc[j], fal, fbh, dacc[j]);
                }
            }
        }
        CP_WAIT0(); __syncthreads();
    }

    // ---- theta = tfin + dacc  (into Hsum buffer, stride HS_LD) ----
    float* th = Hs;
#pragma unroll
    for (int j = 0; j < 3; j++) {
        const int n = ng3 + 4 * j;
        if (n < 10) {
            wmma::store_matrix_sync(wscr, dacc[j], 16, wmma::mem_row_major);
            __syncwarp();
#pragma unroll
            for (int e = 0; e < 8; e++) {
                int idx = lane * 8 + e;
                int r = idx >> 4, c = idx & 15;
                th[(dm * 16 + r) * HS_LD + n * 16 + c] =
                    wscr[r * 16 + c] + g_tfin[n * 16 + c];
            }
            __syncwarp();
        }
    }
    __syncthreads();

    // ---- epilogue: rot6d -> rotmat, betas, camera ----
    float* out_rot  = out;
    float* out_beta = out + (size_t)nrows * 216;
    float* out_cam  = out + (size_t)nrows * 226;

    for (int idx = tid; idx < MR * 24; idx += NT) {
        int r = idx / 24, g = idx - 24 * r;
        const float* tp = &th[r * HS_LD + g * 6];
        float a1x = tp[0], a2x = tp[1];
        float a1y = tp[2], a2y = tp[3];
        float a1z = tp[4], a2z = tp[5];
        float n1 = sqrtf(a1x * a1x + a1y * a1y + a1z * a1z);
        float i1 = 1.f / fmaxf(n1, 1e-12f);
        float b1x = a1x * i1, b1y = a1y * i1, b1z = a1z * i1;
        float d = b1x * a2x + b1y * a2y + b1z * a2z;
        float c2x = a2x - d * b1x, c2y = a2y - d * b1y, c2z = a2z - d * b1z;
        float n2 = sqrtf(c2x * c2x + c2y * c2y + c2z * c2z);
        float i2 = 1.f / fmaxf(n2, 1e-12f);
        float b2x = c2x * i2, b2y = c2y * i2, b2z = c2z * i2;
        float b3x = b1y * b2z - b1z * b2y;
        float b3y = b1z * b2x - b1x * b2z;
        float b3z = b1x * b2y - b1y * b2x;
        float* o = out_rot + (size_t)(row0 + r) * 216 + g * 9;
        o[0] = b1x; o[1] = b2x; o[2] = b3x;
        o[3] = b1y; o[4] = b2y; o[5] = b3y;
        o[6] = b1z; o[7] = b2z; o[8] = b3z;
    }
    for (int idx = tid; idx < MR * 13; idx += NT) {
        int r = idx / 13, c = idx - 13 * r;
        if (c < 10)
            out_beta[(size_t)(row0 + r) * 10 + c] = th[r * HS_LD + 144 + c];
        else
            out_cam[(size_t)(row0 + r) * 3 + (c - 10)] = th[r * HS_LD + 154 + (c - 10)];
    }
}

// ---------------- launch ----------------
extern "C" void kernel_launch(void* const* d_in, const int* in_sizes, int n_in,
                              void* d_out, int out_size) {
    const float* x    = (const float*)d_in[0];
    const float* W1   = (const float*)d_in[2];
    const float* b1   = (const float*)d_in[3];
    const float* W2   = (const float*)d_in[4];
    const float* b2   = (const float*)d_in[5];
    const float* W3   = (const float*)d_in[6];
    const float* b3   = (const float*)d_in[7];
    const float* icr  = (const float*)d_in[8];
    const float* ish  = (const float*)d_in[9];
    const float* icam = (const float*)d_in[10];
    float* out = (float*)d_out;

    int nrows = in_sizes[0] / 256;  // 115200

    prep_k<<<513, 256>>>(W1, b1, W2, b2, W3, b3, icr, ish, icam);

    cudaFuncSetAttribute(detr_wmma, cudaFuncAttributeMaxDynamicSharedMemorySize, SMEM_SZ);
    detr_wmma<<<nrows / MR, NT, SMEM_SZ>>>(x, out, nrows);
}

// round 14
// speedup vs baseline: 2.2219x; 1.6840x over previous
#include <cuda_runtime.h>
#include <cuda_bf16.h>
#include <cstdint>

// ============================================================================
// DETRsmpl head, raw mma.sync m16n8k16 bf16 3-term split, sm_103 base.
// R14: known fragment layouts -> register-direct epilogue, Hsum in registers,
//      8 interleaved acc chains/warp, 64-row k-chunks (82KB smem freed).
//   u0 = x@W1a ; h_i = relu(u_i + c1 + i*cvec) ; u_{i+1} = u_i + h_i@W231
//   theta = (theta0 + 3 b23) + (h0+h1+h2)@W23
// 64 rows/CTA, 1800 CTAs, 512 threads.
// ============================================================================

#define NT 512
#define MR 64
#define HLD 264        // panel stride elements (528 bytes)
#define HLDB 528
#define THLD 164       // theta f32 stride

// smem byte offsets
#define OFF_HH  0           // Hh 33792
#define OFF_HL  33792       // Hl 33792
#define OFF_B   67584       // 2 slots x 67584 (hi 33792 | lo 33792), 64 k-rows
#define OFF_SB  202752      // bias 3 x 256 f32 = 3072
#define SMEM_SZ 205824

__device__ __nv_bfloat16 g_W1h[256 * 256];
__device__ __nv_bfloat16 g_W1l[256 * 256];
__device__ __nv_bfloat16 g_W231h[256 * 256];
__device__ __nv_bfloat16 g_W231l[256 * 256];
__device__ __nv_bfloat16 g_W23h[256 * 192];
__device__ __nv_bfloat16 g_W23l[256 * 192];
__device__ float g_cb[3 * 256];
__device__ float g_tfin[160];

// ---------------- low-level helpers ----------------
#define CP16(dst, src) asm volatile("cp.async.cg.shared.global [%0], [%1], 16;" :: "r"(dst), "l"(src))
#define CP_COMMIT()    asm volatile("cp.async.commit_group;" ::: "memory")
#define CP_WAIT0()     asm volatile("cp.async.wait_group 0;" ::: "memory")

#define LDSM_X4(R, addr) \
    asm volatile("ldmatrix.sync.aligned.m8n8.x4.shared.b16 {%0,%1,%2,%3}, [%4];" \
        : "=r"((R)[0]), "=r"((R)[1]), "=r"((R)[2]), "=r"((R)[3]) : "r"(addr))

#define LDSM_X4T(R, addr) \
    asm volatile("ldmatrix.sync.aligned.m8n8.x4.trans.shared.b16 {%0,%1,%2,%3}, [%4];" \
        : "=r"((R)[0]), "=r"((R)[1]), "=r"((R)[2]), "=r"((R)[3]) : "r"(addr))

#define MMA_BF16(C, A, B0, B1) \
    asm volatile("mma.sync.aligned.m16n8k16.row.col.f32.bf16.bf16.f32 " \
        "{%0,%1,%2,%3}, {%4,%5,%6,%7}, {%8,%9}, {%0,%1,%2,%3};" \
        : "+f"((C)[0]), "+f"((C)[1]), "+f"((C)[2]), "+f"((C)[3]) \
        : "r"((A)[0]), "r"((A)[1]), "r"((A)[2]), "r"((A)[3]), "r"(B0), "r"(B1))

__device__ __forceinline__ uint32_t pk2(__nv_bfloat16 a, __nv_bfloat16 b) {
    return (uint32_t)__bfloat16_as_ushort(a) | ((uint32_t)__bfloat16_as_ushort(b) << 16);
}

__device__ __forceinline__ void splitstore4(__nv_bfloat16* ph, __nv_bfloat16* pl, float4 v) {
    __nv_bfloat16 h0 = __float2bfloat16(v.x), h1 = __float2bfloat16(v.y);
    __nv_bfloat16 h2 = __float2bfloat16(v.z), h3 = __float2bfloat16(v.w);
    __nv_bfloat16 l0 = __float2bfloat16(v.x - __bfloat162float(h0));
    __nv_bfloat16 l1 = __float2bfloat16(v.y - __bfloat162float(h1));
    __nv_bfloat16 l2 = __float2bfloat16(v.z - __bfloat162float(h2));
    __nv_bfloat16 l3 = __float2bfloat16(v.w - __bfloat162float(h3));
    *reinterpret_cast<uint2*>(ph) = make_uint2(pk2(h0, h1), pk2(h2, h3));
    *reinterpret_cast<uint2*>(pl) = make_uint2(pk2(l0, l1), pk2(l2, l3));
}

// ---------------- fused prep kernel (R13 verbatim) ----------------
__global__ void prep_k(const float* __restrict__ W1, const float* __restrict__ b1,
                       const float* __restrict__ W2, const float* __restrict__ b2,
                       const float* __restrict__ W3, const float* __restrict__ b3,
                       const float* __restrict__ icr, const float* __restrict__ ish,
                       const float* __restrict__ icam) {
    __shared__ float srow[192];
    __shared__ float sth[160];
    int b = blockIdx.x, t = threadIdx.x;
    if (b < 256) {
        float v = W1[b * 256 + t];
        __nv_bfloat16 h = __float2bfloat16(v);
        __nv_bfloat16 l = __float2bfloat16(v - __bfloat162float(h));
        g_W1h[b * 256 + t] = h;
        g_W1l[b * 256 + t] = l;
    } else if (b < 512) {
        int k = b - 256;
        if (t < 192) {
            float s0 = 0, s1 = 0, s2 = 0, s3 = 0;
            if (t < 157) {
                for (int m = 0; m < 256; m += 4) {
                    s0 = fmaf(W2[k * 256 + m + 0], W3[(m + 0) * 157 + t], s0);
                    s1 = fmaf(W2[k * 256 + m + 1], W3[(m + 1) * 157 + t], s1);
                    s2 = fmaf(W2[k * 256 + m + 2], W3[(m + 2) * 157 + t], s2);
                    s3 = fmaf(W2[k * 256 + m + 3], W3[(m + 3) * 157 + t], s3);
                }
            }
            float v = (s0 + s1) + (s2 + s3);
            srow[t] = v;
            __nv_bfloat16 h = __float2bfloat16(v);
            __nv_bfloat16 l = __float2bfloat16(v - __bfloat162float(h));
            g_W23h[k * 192 + t] = h;
            g_W23l[k * 192 + t] = l;
        }
        __syncthreads();
        float s = 0.f;
        for (int j = 0; j < 157; j++)
            s = fmaf(srow[j], W1[(256 + j) * 256 + t], s);
        __nv_bfloat16 h = __float2bfloat16(s);
        __nv_bfloat16 l = __float2bfloat16(s - __bfloat162float(h));
        g_W231h[k * 256 + t] = h;
        g_W231l[k * 256 + t] = l;
    } else {
        if (t < 160) {
            float v = 0.f;
            if (t < 144) v = icr[t];
            else if (t < 154) v = ish[t - 144];
            else if (t < 157) v = icam[t - 154];
            sth[t] = v;
            float s = 0.f;
            if (t < 157) {
                s = b3[t];
                for (int m = 0; m < 256; m++)
                    s = fmaf(b2[m], W3[m * 157 + t], s);
            }
            srow[t] = s;
            g_tfin[t] = v + 3.f * s;
        }
        __syncthreads();
        float c1 = b1[t];
        float cv = 0.f;
        for (int j = 0; j < 157; j++) {
            float w = W1[(256 + j) * 256 + t];
            c1 = fmaf(sth[j], w, c1);
            cv = fmaf(srow[j], w, cv);
        }
        g_cb[0 * 256 + t] = c1;
        g_cb[1 * 256 + t] = c1 + cv;
        g_cb[2 * 256 + t] = c1 + 2.f * cv;
    }
}

// ---------------- main kernel ----------------
__global__ __launch_bounds__(NT, 1)
void detr_mma(const float* __restrict__ x, float* __restrict__ out, int nrows) {
    extern __shared__ char smc[];
    float* sbias = reinterpret_cast<float*>(smc + OFF_SB);

    const int tid = threadIdx.x;
    const int w = tid >> 5, lane = tid & 31;
    const int mg = w >> 3, ng = w & 7;           // u-GEMM: warp tile 2m x 2n(16)
    const int row0 = blockIdx.x * MR;

    const uint32_t sbase = (uint32_t)__cvta_generic_to_shared(smc);
    const uint32_t sHh = sbase + OFF_HH;
    const uint32_t sB  = sbase + OFF_B;

    // ldmatrix lane address components (canonical sm_80 mapping)
    const uint32_t rowA = lane & 15;                 // A: lanes 0-15 rows, 16-31 rows @k+8
    const uint32_t koffA = (lane >> 4) << 3;
    const uint32_t rowB = (lane & 7) + ((lane >> 3) & 1) * 8;   // B: k-row within chunk
    const uint32_t colB = ((lane >> 4) & 1) << 3;               // n offset 0/8

    // stage a 64-row x 256-col (hi|lo) B chunk: 4096 CP16, 8/thread
    auto stageB = [&](const __nv_bfloat16* hi, const __nv_bfloat16* lo, int kc, int buf) {
        uint32_t dbase = sB + buf * 67584;
#pragma unroll
        for (int i = 0; i < 8; i++) {
            int idx = tid + i * NT;                 // 0..4095
            int half = idx >> 11, e = idx & 2047;
            int row = e >> 5, col = e & 31;         // 64 rows x 32 groups
            const __nv_bfloat16* src = (half ? lo : hi) + (size_t)(kc * 64 + row) * 256 + col * 8;
            uint32_t dst = dbase + half * 33792 + row * HLDB + col * 16;
            CP16(dst, src);
        }
    };
    // stage a 64-row x 192-col (hi|lo) chunk (W23): 3072 CP16, 6/thread
    auto stageBd = [&](int kc, int buf) {
        uint32_t dbase = sB + buf * 67584;
#pragma unroll
        for (int i = 0; i < 6; i++) {
            int idx = tid + i * NT;                 // 0..3071
            int half = idx >= 1536, e = idx - half * 1536;
            int row = e / 24, col = e - row * 24;   // 64 rows x 24 groups
            const __nv_bfloat16* src = (half ? g_W23l : g_W23h) + (size_t)(kc * 64 + row) * 192 + col * 8;
            uint32_t dst = dbase + half * 33792 + row * HLDB + col * 16;
            CP16(dst, src);
        }
    };

    float acc[2][2][2][4];    // [mi][nj][q][4]
    float hsum[2][2][2][4];

    // u/W231 chunk: 64 k-rows = 4 k16 steps, 24 MMAs per step, term-major
    auto mmaChunk = [&](int kc, int buf) {
        const uint32_t Bh = sB + buf * 67584;
        const uint32_t Bl = Bh + 33792;
#pragma unroll
        for (int ks = 0; ks < 4; ks++) {
            uint32_t ah[2][4], al[2][4], bh[2][4], bl[2][4];
#pragma unroll
            for (int mi = 0; mi < 2; mi++) {
                uint32_t aaddr = sHh + ((mg * 2 + mi) * 16 + rowA) * HLDB
                               + (kc * 64 + ks * 16 + koffA) * 2;
                LDSM_X4(ah[mi], aaddr);
                LDSM_X4(al[mi], aaddr + 33792);
            }
#pragma unroll
            for (int nj = 0; nj < 2; nj++) {
                uint32_t boff = (ks * 16 + rowB) * HLDB + ((ng * 2 + nj) * 16 + colB) * 2;
                LDSM_X4T(bh[nj], Bh + boff);
                LDSM_X4T(bl[nj], Bl + boff);
            }
            // hh terms (8 independent)
#pragma unroll
            for (int mi = 0; mi < 2; mi++)
#pragma unroll
                for (int nj = 0; nj < 2; nj++) {
                    MMA_BF16(acc[mi][nj][0], ah[mi], bh[nj][0], bh[nj][1]);
                    MMA_BF16(acc[mi][nj][1], ah[mi], bh[nj][2], bh[nj][3]);
                }
            // hl terms
#pragma unroll
            for (int mi = 0; mi < 2; mi++)
#pragma unroll
                for (int nj = 0; nj < 2; nj++) {
                    MMA_BF16(acc[mi][nj][0], ah[mi], bl[nj][0], bl[nj][1]);
                    MMA_BF16(acc[mi][nj][1], ah[mi], bl[nj][2], bl[nj][3]);
                }
            // lh terms
#pragma unroll
            for (int mi = 0; mi < 2; mi++)
#pragma unroll
                for (int nj = 0; nj < 2; nj++) {
                    MMA_BF16(acc[mi][nj][0], al[mi], bh[nj][0], bh[nj][1]);
                    MMA_BF16(acc[mi][nj][1], al[mi], bh[nj][2], bh[nj][3]);
                }
        }
    };

    // ---- bias preload + stage W1a chunk0 + x split into panels ----
    for (int i = tid; i < 768; i += NT) sbias[i] = g_cb[i];
    stageB(g_W1h, g_W1l, 0, 0); CP_COMMIT();
    {
        const int r = tid >> 3, c0 = tid & 7;
        const float* xr = x + (size_t)(row0 + r) * 256;
        __nv_bfloat16* Hhp = reinterpret_cast<__nv_bfloat16*>(smc + OFF_HH);
        __nv_bfloat16* Hlp = reinterpret_cast<__nv_bfloat16*>(smc + OFF_HL);
#pragma unroll
        for (int q = 0; q < 8; q++) {
            const int c4 = c0 + 8 * q;
            float4 v = *reinterpret_cast<const float4*>(xr + c4 * 4);
            splitstore4(&Hhp[r * HLD + c4 * 4], &Hlp[r * HLD + c4 * 4], v);
        }
    }
    CP_WAIT0(); __syncthreads();

    // ---- phase A: acc = x @ W1a (4 chunks) ----
#pragma unroll
    for (int mi = 0; mi < 2; mi++)
#pragma unroll
        for (int nj = 0; nj < 2; nj++)
#pragma unroll
            for (int q = 0; q < 2; q++)
#pragma unroll
                for (int e = 0; e < 4; e++) acc[mi][nj][q][e] = 0.f;

    for (int kc = 0; kc < 4; kc++) {
        if (kc < 3) { stageB(g_W1h, g_W1l, kc + 1, (kc + 1) & 1); CP_COMMIT(); }
        mmaChunk(kc, kc & 1);
        CP_WAIT0(); __syncthreads();
    }

    // ---- 3 iterations ----
    for (int it = 0; it < 3; it++) {
        if (it < 2) stageB(g_W231h, g_W231l, 0, 0); else stageBd(0, 0);
        CP_COMMIT();

        // register-direct conversion: h = relu(acc + bias); hsum in regs; panels <- h / hfin
#pragma unroll
        for (int mi = 0; mi < 2; mi++)
#pragma unroll
            for (int nj = 0; nj < 2; nj++)
#pragma unroll
                for (int q = 0; q < 2; q++) {
                    float* c = acc[mi][nj][q];
                    float* hs = hsum[mi][nj][q];
                    const int colg = (ng * 2 + nj) * 16 + q * 8 + (lane & 3) * 2;
                    const float b0 = sbias[it * 256 + colg];
                    const float b1 = sbias[it * 256 + colg + 1];
                    float h0 = fmaxf(c[0] + b0, 0.f);
                    float h1 = fmaxf(c[1] + b1, 0.f);
                    float h2 = fmaxf(c[2] + b0, 0.f);
                    float h3 = fmaxf(c[3] + b1, 0.f);
                    if (it == 0)      { hs[0] = h0; hs[1] = h1; hs[2] = h2; hs[3] = h3; }
                    else if (it == 1) { hs[0] += h0; hs[1] += h1; hs[2] += h2; hs[3] += h3; }
                    else { h0 += hs[0]; h1 += hs[1]; h2 += hs[2]; h3 += hs[3]; }
                    const int r0 = (mg * 2 + mi) * 16 + (lane >> 2);
                    __nv_bfloat16 p0 = __float2bfloat16(h0), p1 = __float2bfloat16(h1);
                    __nv_bfloat16 p2 = __float2bfloat16(h2), p3 = __float2bfloat16(h3);
                    uint32_t* d0 = reinterpret_cast<uint32_t*>(smc + OFF_HH + r0 * HLDB + colg * 2);
                    uint32_t* d2 = reinterpret_cast<uint32_t*>(smc + OFF_HH + (r0 + 8) * HLDB + colg * 2);
                    d0[0] = pk2(p0, p1);
                    d2[0] = pk2(p2, p3);
                    uint32_t* l0 = reinterpret_cast<uint32_t*>(smc + OFF_HL + r0 * HLDB + colg * 2);
                    uint32_t* l2 = reinterpret_cast<uint32_t*>(smc + OFF_HL + (r0 + 8) * HLDB + colg * 2);
                    l0[0] = pk2(__float2bfloat16(h0 - __bfloat162float(p0)),
                                __float2bfloat16(h1 - __bfloat162float(p1)));
                    l2[0] = pk2(__float2bfloat16(h2 - __bfloat162float(p2)),
                                __float2bfloat16(h3 - __bfloat162float(p3)));
                }
        CP_WAIT0(); __syncthreads();

        if (it < 2) {
            for (int kc = 0; kc < 4; kc++) {
                if (kc < 3) { stageB(g_W231h, g_W231l, kc + 1, (kc + 1) & 1); CP_COMMIT(); }
                mmaChunk(kc, kc & 1);
                CP_WAIT0(); __syncthreads();
            }
        }
    }

    // ---- delta = Hsum_panels @ W23 (4m x 12n; warp: 1m x 3n(16)) ----
    const int dm = w & 3, ng3 = w >> 2;
    float dacc[3][2][4];
#pragma unroll
    for (int j = 0; j < 3; j++)
#pragma unroll
        for (int q = 0; q < 2; q++)
#pragma unroll
            for (int e = 0; e < 4; e++) dacc[j][q][e] = 0.f;

    for (int kc = 0; kc < 4; kc++) {
        if (kc < 3) { stageBd(kc + 1, (kc + 1) & 1); CP_COMMIT(); }
        {
            const uint32_t Bh = sB + (kc & 1) * 67584;
            const uint32_t Bl = Bh + 33792;
#pragma unroll
            for (int ks = 0; ks < 4; ks++) {
                uint32_t ah[4], al[4], bh[3][4], bl[3][4];
                uint32_t aaddr = sHh + (dm * 16 + rowA) * HLDB
                               + (kc * 64 + ks * 16 + koffA) * 2;
                LDSM_X4(ah, aaddr);
                LDSM_X4(al, aaddr + 33792);
#pragma unroll
                for (int j = 0; j < 3; j++) {
                    uint32_t boff = (ks * 16 + rowB) * HLDB + ((ng3 + 4 * j) * 16 + colB) * 2;
                    LDSM_X4T(bh[j], Bh + boff);
                    LDSM_X4T(bl[j], Bl + boff);
                }
#pragma unroll
                for (int j = 0; j < 3; j++) {
                    MMA_BF16(dacc[j][0], ah, bh[j][0], bh[j][1]);
                    MMA_BF16(dacc[j][1], ah, bh[j][2], bh[j][3]);
                }
#pragma unroll
                for (int j = 0; j < 3; j++) {
                    MMA_BF16(dacc[j][0], ah, bl[j][0], bl[j][1]);
                    MMA_BF16(dacc[j][1], ah, bl[j][2], bl[j][3]);
                }
#pragma unroll
                for (int j = 0; j < 3; j++) {
                    MMA_BF16(dacc[j][0], al, bh[j][0], bh[j][1]);
                    MMA_BF16(dacc[j][1], al, bh[j][2], bh[j][3]);
                }
            }
        }
        CP_WAIT0(); __syncthreads();
    }

    // ---- theta = tfin + dacc, register-direct into B region (dead) ----
    float* th = reinterpret_cast<float*>(smc + OFF_B);
#pragma unroll
    for (int j = 0; j < 3; j++) {
        const int nt = ng3 + 4 * j;
        if (nt < 10) {
#pragma unroll
            for (int q = 0; q < 2; q++) {
                const int colg = nt * 16 + q * 8 + (lane & 3) * 2;
                const int r0 = dm * 16 + (lane >> 2);
                const float t0 = g_tfin[colg], t1 = g_tfin[colg + 1];
                th[r0 * THLD + colg]           = dacc[j][q][0] + t0;
                th[r0 * THLD + colg + 1]       = dacc[j][q][1] + t1;
                th[(r0 + 8) * THLD + colg]     = dacc[j][q][2] + t0;
                th[(r0 + 8) * THLD + colg + 1] = dacc[j][q][3] + t1;
            }
        }
    }
    __syncthreads();

    // ---- epilogue: rot6d -> rotmat, betas, camera ----
    float* out_rot  = out;
    float* out_beta = out + (size_t)nrows * 216;
    float* out_cam  = out + (size_t)nrows * 226;

    for (int idx = tid; idx < MR * 24; idx += NT) {
        int r = idx / 24, g = idx - 24 * r;
        const float* tp = &th[r * THLD + g * 6];
        float a1x = tp[0], a2x = tp[1];
        float a1y = tp[2], a2y = tp[3];
        float a1z = tp[4], a2z = tp[5];
        float n1 = sqrtf(a1x * a1x + a1y * a1y + a1z * a1z);
        float i1 = 1.f / fmaxf(n1, 1e-12f);
        float b1x = a1x * i1, b1y = a1y * i1, b1z = a1z * i1;
        float d = b1x * a2x + b1y * a2y + b1z * a2z;
        float c2x = a2x - d * b1x, c2y = a2y - d * b1y, c2z = a2z - d * b1z;
        float n2 = sqrtf(c2x * c2x + c2y * c2y + c2z * c2z);
        float i2 = 1.f / fmaxf(n2, 1e-12f);
        float b2x = c2x * i2, b2y = c2y * i2, b2z = c2z * i2;
        float b3x = b1y * b2z - b1z * b2y;
        float b3y = b1z * b2x - b1x * b2z;
        float b3z = b1x * b2y - b1y * b2x;
        float* o = out_rot + (size_t)(row0 + r) * 216 + g * 9;
        o[0] = b1x; o[1] = b2x; o[2] = b3x;
        o[3] = b1y; o[4] = b2y; o[5] = b3y;
        o[6] = b1z; o[7] = b2z; o[8] = b3z;
    }
    for (int idx = tid; idx < MR * 13; idx += NT) {
        int r = idx / 13, c = idx - 13 * r;
        if (c < 10)
            out_beta[(size_t)(row0 + r) * 10 + c] = th[r * THLD + 144 + c];
        else
            out_cam[(size_t)(row0 + r) * 3 + (c - 10)] = th[r * THLD + 154 + (c - 10)];
    }
}

// ---------------- launch ----------------
extern "C" void kernel_launch(void* const* d_in, const int* in_sizes, int n_in,
                              void* d_out, int out_size) {
    const float* x    = (const float*)d_in[0];
    const float* W1   = (const float*)d_in[2];
    const float* b1   = (const float*)d_in[3];
    const float* W2   = (const float*)d_in[4];
    const float* b2   = (const float*)d_in[5];
    const float* W3   = (const float*)d_in[6];
    const float* b3   = (const float*)d_in[7];
    const float* icr  = (const float*)d_in[8];
    const float* ish  = (const float*)d_in[9];
    const float* icam = (const float*)d_in[10];
    float* out = (float*)d_out;

    int nrows = in_sizes[0] / 256;  // 115200

    prep_k<<<513, 256>>>(W1, b1, W2, b2, W3, b3, icr, ish, icam);

    cudaFuncSetAttribute(detr_mma, cudaFuncAttributeMaxDynamicSharedMemorySize, SMEM_SZ);
    detr_mma<<<nrows / MR, NT, SMEM_SZ>>>(x, out, nrows);
}